// round 1
// baseline (speedup 1.0000x reference)
#include <cuda_runtime.h>

// ---------------- problem constants ----------------
// B=4096, image 1x128x128, G=14, K=4 levels, patch sizes 14/28/56/112
// phi: (4096, 784), what MLP 784->128->256, where MLP 2->128->256, out (4096,256)

#define NB 4096
#define IMG 128
#define WIN 112          // largest patch == union window
#define WSTR 113         // padded shared stride

// ---------------- scratch (device globals; no allocation allowed) ----------------
__device__ float  g_phi[NB * 784];
__device__ float  g_h1w[NB * 128];
__device__ float  g_h1l[NB * 128];
__device__ float  g_h2w[NB * 256];
__device__ float  g_h2l[NB * 256];
// stats layout (doubles): s1w[128] ss1w[128] s1l[128] ss1l[128] s2w[256] ss2w[256] s2l[256] ss2l[256]
__device__ double g_stats[1536];
// bn params (floats), same offsets: scale/shift per feature per BN
__device__ float  g_bn[1536];

// ---------------- kernels ----------------

__global__ void zero_stats_kernel() {
    for (int i = threadIdx.x; i < 1536; i += blockDim.x) g_stats[i] = 0.0;
}

// One block per sample: load 112x112 zero-padded window into smem (coalesced),
// then compute all 4 pooled patches (784 outputs) from shared.
__global__ void foveate_kernel(const float* __restrict__ x, const float* __restrict__ loc) {
    extern __shared__ float sh[];  // WIN * WSTR floats
    const int b = blockIdx.x;
    const float lx = loc[2 * b + 0];
    const float ly = loc[2 * b + 1];
    // coords = int32(0.5*((loc+1)*H)); [:,0]=x(col), [:,1]=y(row); trunc toward zero
    const int cx = (int)(0.5f * ((lx + 1.0f) * 128.0f));
    const int cy = (int)(0.5f * ((ly + 1.0f) * 128.0f));
    const int y0 = cy - 56;
    const int x0 = cx - 56;
    const float* img = x + (size_t)b * (IMG * IMG);

    for (int idx = threadIdx.x; idx < WIN * WIN; idx += blockDim.x) {
        int r = idx / WIN;
        int c = idx - r * WIN;
        int gy = y0 + r, gx = x0 + c;
        float v = 0.0f;
        if ((unsigned)gy < 128u && (unsigned)gx < 128u) v = img[gy * IMG + gx];
        sh[r * WSTR + c] = v;
    }
    __syncthreads();

    float* out = g_phi + (size_t)b * 784;
    for (int idx = threadIdx.x; idx < 784; idx += blockDim.x) {
        int l = idx / 196;
        int rem = idx - l * 196;
        int i = rem / 14;
        int j = rem - i * 14;
        int k = 1 << l;                  // pool factor: 1,2,4,8
        int off = 56 - 7 * k;            // patch start inside window
        int base = (off + i * k) * WSTR + (off + j * k);
        float s = 0.0f;
        for (int ky = 0; ky < k; ky++) {
            int rb = base + ky * WSTR;
            for (int kx = 0; kx < k; kx++) s += sh[rb + kx];
        }
        out[idx] = s * (1.0f / (float)(k * k));
    }
}

// SIMT fp32 tiled GEMM: C[M,N] = act(A)[M,K] @ W[K,N] + bias.
// TRANS: a -> relu(a*bnsc[k] + bnsh[k]) applied on the A-tile load (BN+relu of prev layer).
template <bool TRANS>
__global__ void __launch_bounds__(256, 4)
gemm_kernel(const float* __restrict__ A, const float* __restrict__ W,
            const float* __restrict__ bias, float* __restrict__ C,
            int M, int N, int K,
            const float* __restrict__ bnsc, const float* __restrict__ bnsh) {
    constexpr int BM = 64, BN = 64, BK = 16, TM = 4, TN = 4;
    __shared__ float As[BK * (BM + 1)];
    __shared__ float Bs[BK * BN];

    const int tid = threadIdx.x;
    const int m0 = blockIdx.y * BM;
    const int n0 = blockIdx.x * BN;
    const int tx = tid % (BN / TN);   // 16
    const int ty = tid / (BN / TN);   // 16

    float acc[TM][TN];
#pragma unroll
    for (int i = 0; i < TM; i++)
#pragma unroll
        for (int j = 0; j < TN; j++) acc[i][j] = 0.0f;

    for (int k0 = 0; k0 < K; k0 += BK) {
        // A tile: BM x BK (coalesced along k), stored transposed with pad
#pragma unroll
        for (int it = 0; it < (BM * BK) / 256; ++it) {
            int ka = tid % BK;
            int ma = tid / BK + it * (256 / BK);
            float v = A[(size_t)(m0 + ma) * K + (k0 + ka)];
            if (TRANS) v = fmaxf(fmaf(v, bnsc[k0 + ka], bnsh[k0 + ka]), 0.0f);
            As[ka * (BM + 1) + ma] = v;
        }
        // B tile: BK x BN (coalesced along n)
#pragma unroll
        for (int it = 0; it < (BK * BN) / 256; ++it) {
            int nb = tid % BN;
            int kb = tid / BN + it * (256 / BN);
            Bs[kb * BN + nb] = W[(size_t)(k0 + kb) * N + (n0 + nb)];
        }
        __syncthreads();

#pragma unroll
        for (int kk = 0; kk < BK; kk++) {
            float a[TM], bv[TN];
#pragma unroll
            for (int i = 0; i < TM; i++) a[i] = As[kk * (BM + 1) + ty * TM + i];
#pragma unroll
            for (int j = 0; j < TN; j++) bv[j] = Bs[kk * BN + tx * TN + j];
#pragma unroll
            for (int i = 0; i < TM; i++)
#pragma unroll
                for (int j = 0; j < TN; j++) acc[i][j] = fmaf(a[i], bv[j], acc[i][j]);
        }
        __syncthreads();
    }

#pragma unroll
    for (int i = 0; i < TM; i++) {
        int m = m0 + ty * TM + i;
#pragma unroll
        for (int j = 0; j < TN; j++) {
            int n = n0 + tx * TN + j;
            C[(size_t)m * N + n] = acc[i][j] + bias[n];
        }
    }
}

// where layer1: h1l[b,j] = loc[b,0]*W[0,j] + loc[b,1]*W[1,j] + b1[j]
__global__ void where1_kernel(const float* __restrict__ loc,
                              const float* __restrict__ W,
                              const float* __restrict__ bias) {
    int idx = blockIdx.x * blockDim.x + threadIdx.x;  // NB*128
    int b = idx >> 7;
    int j = idx & 127;
    g_h1l[idx] = fmaf(loc[2 * b], W[j], fmaf(loc[2 * b + 1], W[128 + j], bias[j]));
}

// column sums & sum-of-squares, N = blockDim.x features, coalesced rows
__global__ void colstats_kernel(const float* __restrict__ h, int rowsPerBlock,
                                double* __restrict__ sum, double* __restrict__ sumsq) {
    int Nf = blockDim.x;
    int col = threadIdx.x;
    int r0 = blockIdx.x * rowsPerBlock;
    float s = 0.0f, s2 = 0.0f;
    const float* p = h + (size_t)r0 * Nf + col;
    for (int r = 0; r < rowsPerBlock; r++) {
        float v = p[(size_t)r * Nf];
        s += v;
        s2 = fmaf(v, v, s2);
    }
    atomicAdd(&sum[col], (double)s);
    atomicAdd(&sumsq[col], (double)s2);
}

__global__ void finalize_kernel(const double* __restrict__ s, const double* __restrict__ ss,
                                const float* __restrict__ g, const float* __restrict__ be,
                                float* __restrict__ sc, float* __restrict__ sh) {
    int j = threadIdx.x;
    double m = s[j] * (1.0 / (double)NB);
    double var = ss[j] * (1.0 / (double)NB) - m * m;
    float scale = g[j] * rsqrtf((float)var + 1e-5f);
    sc[j] = scale;
    sh[j] = be[j] - (float)m * scale;
}

// out = relu( BN2w(h2w) + BN2l(h2l) )
__global__ void final_kernel(float* __restrict__ out) {
    int idx = blockIdx.x * blockDim.x + threadIdx.x;  // NB*256
    int j = idx & 255;
    float vw = fmaf(g_h2w[idx], g_bn[512 + j], g_bn[768 + j]);
    float vl = fmaf(g_h2l[idx], g_bn[1024 + j], g_bn[1280 + j]);
    out[idx] = fmaxf(vw + vl, 0.0f);
}

// ---------------- launch ----------------

extern "C" void kernel_launch(void* const* d_in, const int* in_sizes, int n_in,
                              void* d_out, int out_size) {
    const float* x    = (const float*)d_in[0];
    const float* loc  = (const float*)d_in[1];
    const float* wW1  = (const float*)d_in[2];
    const float* wb1  = (const float*)d_in[3];
    const float* wg1  = (const float*)d_in[4];
    const float* wbe1 = (const float*)d_in[5];
    const float* wW2  = (const float*)d_in[6];
    const float* wb2  = (const float*)d_in[7];
    const float* wg2  = (const float*)d_in[8];
    const float* wbe2 = (const float*)d_in[9];
    const float* lW1  = (const float*)d_in[10];
    const float* lb1  = (const float*)d_in[11];
    const float* lg1  = (const float*)d_in[12];
    const float* lbe1 = (const float*)d_in[13];
    const float* lW2  = (const float*)d_in[14];
    const float* lb2  = (const float*)d_in[15];
    const float* lg2  = (const float*)d_in[16];
    const float* lbe2 = (const float*)d_in[17];
    float* out = (float*)d_out;

    // resolve device-global addresses (not allocation; idempotent)
    float *phi, *h1w, *h1l, *h2w, *h2l, *bn;
    double* stats;
    cudaGetSymbolAddress((void**)&phi,   g_phi);
    cudaGetSymbolAddress((void**)&h1w,   g_h1w);
    cudaGetSymbolAddress((void**)&h1l,   g_h1l);
    cudaGetSymbolAddress((void**)&h2w,   g_h2w);
    cudaGetSymbolAddress((void**)&h2l,   g_h2l);
    cudaGetSymbolAddress((void**)&stats, g_stats);
    cudaGetSymbolAddress((void**)&bn,    g_bn);

    const int smem_fov = WIN * WSTR * sizeof(float);  // 50624 B > 48KB default
    cudaFuncSetAttribute(foveate_kernel, cudaFuncAttributeMaxDynamicSharedMemorySize, smem_fov);

    zero_stats_kernel<<<1, 512>>>();

    // 1) foveate -> phi
    foveate_kernel<<<NB, 256, smem_fov>>>(x, loc);

    // 2) gemm1 what: h1w = phi @ W1 + b1   (M=4096, N=128, K=784)
    gemm_kernel<false><<<dim3(128 / 64, NB / 64), 256>>>(phi, wW1, wb1, h1w, NB, 128, 784, nullptr, nullptr);

    // where layer1 (K=2, trivial)
    where1_kernel<<<(NB * 128) / 256, 256>>>(loc, lW1, lb1);

    // 3) BN1 stats + finalize (both paths)
    colstats_kernel<<<32, 128>>>(h1w, 128, stats + 0,   stats + 128);
    colstats_kernel<<<32, 128>>>(h1l, 128, stats + 256, stats + 384);
    finalize_kernel<<<1, 128>>>(stats + 0,   stats + 128, wg1, wbe1, bn + 0,   bn + 128);
    finalize_kernel<<<1, 128>>>(stats + 256, stats + 384, lg1, lbe1, bn + 256, bn + 384);

    // 4) gemm2: h2 = relu(BN1(h1)) @ W2 + b2   (M=4096, N=256, K=128)
    gemm_kernel<true><<<dim3(256 / 64, NB / 64), 256>>>(h1w, wW2, wb2, h2w, NB, 256, 128, bn + 0,   bn + 128);
    gemm_kernel<true><<<dim3(256 / 64, NB / 64), 256>>>(h1l, lW2, lb2, h2l, NB, 256, 128, bn + 256, bn + 384);

    // 5) BN2 stats + finalize
    colstats_kernel<<<32, 256>>>(h2w, 128, stats + 512,  stats + 768);
    colstats_kernel<<<32, 256>>>(h2l, 128, stats + 1024, stats + 1280);
    finalize_kernel<<<1, 256>>>(stats + 512,  stats + 768,  wg2, wbe2, bn + 512,  bn + 768);
    finalize_kernel<<<1, 256>>>(stats + 1024, stats + 1280, lg2, lbe2, bn + 1024, bn + 1280);

    // 6) out = relu(BN2w(h2w) + BN2l(h2l))
    final_kernel<<<NB, 256>>>(out);
}